// round 2
// baseline (speedup 1.0000x reference)
#include <cuda_runtime.h>

#define C      128
#define CH     64          // c/2
#define KNB    16
#define CHUNK  4
#define NCHUNK (KNB/CHUNK)
#define PB     4           // points per warp
#define WARPS  8
#define THREADS 256
#define NPTS   (8*4096)

// Scratch (device globals — no allocation allowed in kernel_launch)
__device__ float g_B[C*C];     // B[i][j]  = sum_o wq[o][i] * wk[o][j]
__device__ float g_wvT[C*C];   // wvT[i][o] = wv[o][i]

__global__ void precompute_kernel(const float* __restrict__ wq,
                                  const float* __restrict__ wk,
                                  const float* __restrict__ wv) {
    const int i = blockIdx.x;   // 0..127
    const int j = threadIdx.x;  // 0..127
    float acc = 0.f;
#pragma unroll
    for (int o = 0; o < CH; ++o)
        acc = fmaf(wq[o*C + i], wk[o*C + j], acc);
    g_B[i*C + j]   = acc;
    g_wvT[i*C + j] = wv[j*C + i];
}

__device__ __forceinline__ float dot4(const float4 a, const float4 b) {
    float t = a.x * b.x;
    t = fmaf(a.y, b.y, t);
    t = fmaf(a.z, b.z, t);
    t = fmaf(a.w, b.w, t);
    return t;
}

__global__ void __launch_bounds__(THREADS, 3)
attn_kernel(const float* __restrict__ fc,   // [NPTS][C]      fea_center
            const float* __restrict__ fn,   // [NPTS][KNB][C] fea_near
            float* __restrict__ out)        // [NPTS][C]
{
    // sh_xy holds center features during phases A/middle, then is overwritten
    // per-point with the softmax-weighted feature y (consumed by Phase C).
    __shared__ float sh_xy[WARPS][PB*C];

    const int warp = threadIdx.x >> 5;
    const int lane = threadIdx.x & 31;
    const int p0   = (blockIdx.x * WARPS + warp) * PB;

    float* xy = sh_xy[warp];
    const int l4 = lane * 4;

    // ---- stage center features ----
#pragma unroll
    for (int p = 0; p < PB; ++p)
        *(float4*)(xy + p*C + l4) =
            *(const float4*)(fc + (size_t)(p0 + p)*C + l4);
    __syncwarp();

    // ---- Phase A: u[p][j] = sum_i B[i][j] * xc[p][i] (lane owns j = l4..l4+3) ----
    float4 u4[PB];
#pragma unroll
    for (int p = 0; p < PB; ++p) u4[p] = make_float4(0.f, 0.f, 0.f, 0.f);
#pragma unroll 2
    for (int i0 = 0; i0 < C; i0 += 4) {
        float4 c4[PB];
#pragma unroll
        for (int p = 0; p < PB; ++p)
            c4[p] = *(const float4*)(xy + p*C + i0);   // shared broadcast
#pragma unroll
        for (int di = 0; di < 4; ++di) {
            const float4 b4 = *(const float4*)(g_B + (i0 + di)*C + l4);
#pragma unroll
            for (int p = 0; p < PB; ++p) {
                const float cv = (&c4[p].x)[di];
                u4[p].x = fmaf(b4.x, cv, u4[p].x);
                u4[p].y = fmaf(b4.y, cv, u4[p].y);
                u4[p].z = fmaf(b4.z, cv, u4[p].z);
                u4[p].w = fmaf(b4.w, cv, u4[p].w);
            }
        }
    }
    __syncwarp();

    // ---- Middle: online softmax over {16 neighbors, center}, y = sum w_j x_j ----
#pragma unroll 1
    for (int p = 0; p < PB; ++p) {
        const float* xn = fn + (size_t)(p0 + p)*(KNB*C);
        const float4 up = u4[p];
        const float4 c4 = *(const float4*)(xy + p*C + l4);

        // center logit first (its softmax weight is exp(0)=1 under its own max)
        float dc = dot4(up, c4);
#pragma unroll
        for (int off = 16; off; off >>= 1)
            dc += __shfl_xor_sync(0xffffffffu, dc, off);

        float m = dc * 0.125f;        // running max (scaled logit)
        float s = 1.f;                // running sum
        float4 y;
        y.x = c4.x; y.y = c4.y; y.z = c4.z; y.w = c4.w;

        // double-buffered neighbor chunks
        float4 xb[2][CHUNK];
#pragma unroll
        for (int q = 0; q < CHUNK; ++q)
            xb[0][q] = *(const float4*)(xn + q*C + l4);

#pragma unroll
        for (int ck = 0; ck < NCHUNK; ++ck) {
            const int buf = ck & 1;
            if (ck + 1 < NCHUNK) {
#pragma unroll
                for (int q = 0; q < CHUNK; ++q)
                    xb[buf ^ 1][q] =
                        *(const float4*)(xn + ((ck + 1)*CHUNK + q)*C + l4);
            }
            float d[CHUNK];
#pragma unroll
            for (int q = 0; q < CHUNK; ++q)
                d[q] = dot4(up, xb[buf][q]);
#pragma unroll
            for (int off = 16; off; off >>= 1) {
#pragma unroll
                for (int q = 0; q < CHUNK; ++q)
                    d[q] += __shfl_xor_sync(0xffffffffu, d[q], off);
            }
            float mn = m;
#pragma unroll
            for (int q = 0; q < CHUNK; ++q) {
                d[q] *= 0.125f;
                mn = fmaxf(mn, d[q]);
            }
            const float f = __expf(m - mn);
            s *= f;
            y.x *= f; y.y *= f; y.z *= f; y.w *= f;
#pragma unroll
            for (int q = 0; q < CHUNK; ++q) {
                const float w = __expf(d[q] - mn);
                s += w;
                y.x = fmaf(w, xb[buf][q].x, y.x);
                y.y = fmaf(w, xb[buf][q].y, y.y);
                y.z = fmaf(w, xb[buf][q].z, y.z);
                y.w = fmaf(w, xb[buf][q].w, y.w);
            }
            m = mn;
        }
        const float rs = 1.f / s;
        y.x *= rs; y.y *= rs; y.z *= rs; y.w *= rs;
        *(float4*)(xy + p*C + l4) = y;   // overwrite center slot with y
    }
    __syncwarp();

    // ---- Phase C: out[p][o] = sum_i wvT[i][o] * y[p][i] (lane owns o = l4..l4+3) ----
    {
        float4 o4[PB];
#pragma unroll
        for (int p = 0; p < PB; ++p) o4[p] = make_float4(0.f, 0.f, 0.f, 0.f);
#pragma unroll 2
        for (int i0 = 0; i0 < C; i0 += 4) {
            float4 y4[PB];
#pragma unroll
            for (int p = 0; p < PB; ++p)
                y4[p] = *(const float4*)(xy + p*C + i0);   // shared broadcast
#pragma unroll
            for (int di = 0; di < 4; ++di) {
                const float4 w4 = *(const float4*)(g_wvT + (i0 + di)*C + l4);
#pragma unroll
                for (int p = 0; p < PB; ++p) {
                    const float yv = (&y4[p].x)[di];
                    o4[p].x = fmaf(w4.x, yv, o4[p].x);
                    o4[p].y = fmaf(w4.y, yv, o4[p].y);
                    o4[p].z = fmaf(w4.z, yv, o4[p].z);
                    o4[p].w = fmaf(w4.w, yv, o4[p].w);
                }
            }
        }
#pragma unroll
        for (int p = 0; p < PB; ++p)
            *(float4*)(out + (size_t)(p0 + p)*C + l4) = o4[p];
    }
}

extern "C" void kernel_launch(void* const* d_in, const int* in_sizes, int n_in,
                              void* d_out, int out_size) {
    const float* fc = (const float*)d_in[0];   // fea_center [8,4096,1,128]
    const float* fn = (const float*)d_in[1];   // fea_near   [8,4096,16,128]
    const float* wq = (const float*)d_in[2];   // [64,128]
    const float* wk = (const float*)d_in[3];   // [64,128]
    const float* wv = (const float*)d_in[4];   // [128,128]
    float* out = (float*)d_out;                // [8,4096,128]

    precompute_kernel<<<C, C>>>(wq, wk, wv);
    attn_kernel<<<NPTS/(PB*WARPS), THREADS>>>(fc, fn, out);
}